// round 12
// baseline (speedup 1.0000x reference)
#include <cuda_runtime.h>
#include <cuda_bf16.h>
#include <math.h>
#include <stdint.h>

#define NROWS 8192
#define DIM   128
#define BHALF 4096
#define BT    128
#define NT    (NROWS / BT)          // 64
#define NTILES (NT * (NT + 1) / 2)  // 2080
#define POS_DELTA (BHALF / BT)      // 32
#define LOG2E 1.4426950408889634f

// ---------------- global scratch (no allocations allowed) ----------------
__device__ double g_S2, g_POS, g_R1, g_R2;
__device__ unsigned g_ticket;
__device__ double g_rowsum[NROWS];
__device__ __align__(16) uint4 g_bf16[NROWS * 16];      // pre-swizzled bf16 rows (256B/row)

// ---------------- prep: init + bf16 convert (norms == 0.5 exactly) ----------
__global__ void prep_kernel(const float* __restrict__ feat) {
    int t = blockIdx.x * blockDim.x + threadIdx.x;   // one uint4 (8 bf16) per thread
    int row = t >> 4;
    int chunk = t & 15;
    const float4* src = reinterpret_cast<const float4*>(feat + row * DIM + chunk * 8);
    float4 a = src[0], b = src[1];
    if (chunk == 0) g_rowsum[row] = 0.0;
    if (t == 0) { g_S2 = 0.0; g_POS = 0.0; g_R1 = 0.0; g_R2 = 0.0; g_ticket = 0u; }

    __nv_bfloat162 p0 = __floats2bfloat162_rn(a.x, a.y);
    __nv_bfloat162 p1 = __floats2bfloat162_rn(a.z, a.w);
    __nv_bfloat162 p2 = __floats2bfloat162_rn(b.x, b.y);
    __nv_bfloat162 p3 = __floats2bfloat162_rn(b.z, b.w);
    uint4 v;
    v.x = *reinterpret_cast<uint32_t*>(&p0);
    v.y = *reinterpret_cast<uint32_t*>(&p1);
    v.z = *reinterpret_cast<uint32_t*>(&p2);
    v.w = *reinterpret_cast<uint32_t*>(&p3);
    g_bf16[row * 16 + (chunk ^ (row & 7))] = v;   // 16B-granular XOR swizzle
}

// ---------------- helpers ----------------
__device__ __forceinline__ uint32_t smem_u32(const void* p) {
    uint32_t a;
    asm("{ .reg .u64 t; cvta.to.shared.u64 t, %1; cvt.u32.u64 %0, t; }" : "=r"(a) : "l"(p));
    return a;
}
__device__ __forceinline__ void cp_async16(uint32_t saddr, const void* gaddr) {
    asm volatile("cp.async.cg.shared.global [%0], [%1], 16;" :: "r"(saddr), "l"(gaddr));
}
__device__ __forceinline__ void cp_commit() {
    asm volatile("cp.async.commit_group;" ::: "memory");
}
__device__ __forceinline__ void cp_wait_all() {
    asm volatile("cp.async.wait_group 0;" ::: "memory");
}
__device__ __forceinline__ void ldmatrix_x4(uint32_t& r0, uint32_t& r1, uint32_t& r2,
                                            uint32_t& r3, uint32_t addr) {
    asm volatile("ldmatrix.sync.aligned.m8n8.x4.shared.b16 {%0,%1,%2,%3}, [%4];"
                 : "=r"(r0), "=r"(r1), "=r"(r2), "=r"(r3) : "r"(addr));
}
__device__ __forceinline__ void mma_bf16(float& c0, float& c1, float& c2, float& c3,
                                         uint32_t a0, uint32_t a1, uint32_t a2, uint32_t a3,
                                         uint32_t b0, uint32_t b1) {
    asm volatile("mma.sync.aligned.m16n8k16.row.col.f32.bf16.bf16.f32 "
                 "{%0,%1,%2,%3}, {%4,%5,%6,%7}, {%8,%9}, {%0,%1,%2,%3};"
                 : "+f"(c0), "+f"(c1), "+f"(c2), "+f"(c3)
                 : "r"(a0), "r"(a1), "r"(a2), "r"(a3), "r"(b0), "r"(b1));
}
__device__ __forceinline__ float ex2f(float x) {
    float r; asm("ex2.approx.f32 %0, %1;" : "=f"(r) : "f"(x)); return r;
}
__device__ __forceinline__ unsigned long long packf2(float lo, float hi) {
    unsigned long long r;
    asm("mov.b64 %0, {%1, %2};" : "=l"(r) : "f"(lo), "f"(hi));
    return r;
}
__device__ __forceinline__ void unpackf2(unsigned long long v, float& lo, float& hi) {
    asm("mov.b64 {%0, %1}, %2;" : "=f"(lo), "=f"(hi) : "l"(v));
}
__device__ __forceinline__ void fma2acc(unsigned long long& acc, unsigned long long a,
                                        unsigned long long b) {
    asm("fma.rn.f32x2 %0, %1, %2, %0;" : "+l"(acc) : "l"(a), "l"(b));
}
__device__ __forceinline__ void add2acc(unsigned long long& acc, unsigned long long a) {
    asm("add.rn.f32x2 %0, %1, %2;" : "=l"(acc) : "l"(a), "l"(acc));
}

// ---------------- fused tile kernel (R8 structure, 8 warps x 16 rows) -------
// One CTA (256 thr, 8 warps) = one 128x128 triangular tile. Warp w owns rows
// [16w, 16w+16). A hoisted into 32 regs/thread; B streamed as four 32-col
// (8KB) slices through a 2-buffer cp.async ring. No register spills.
__global__ __launch_bounds__(256, 2)
void tile_kernel() {
    const int L = blockIdx.x;
    int I = (int)floorf((2.0f * NT + 1.0f
                         - sqrtf((2.0f * NT + 1.0f) * (2.0f * NT + 1.0f) - 8.0f * (float)L))
                        * 0.5f);
    while (I * NT - I * (I - 1) / 2 > L) --I;
    while ((I + 1) * NT - (I + 1) * I / 2 <= L) ++I;
    const int J = I + (L - (I * NT - I * (I - 1) / 2));

    const bool diagT = (I == J);
    const bool posT  = (J == I + POS_DELTA);

    extern __shared__ unsigned char smem[];
    // [0,32K): A stage, reused as two 8KB B slice buffers after extraction
    float* redRow = reinterpret_cast<float*>(smem + 32768);    // [128]
    float* redCol = reinterpret_cast<float*>(smem + 33280);    // [128]
    float* redS   = reinterpret_cast<float*>(smem + 33792);    // [2]: s2, pos

    const int t = threadIdx.x, wid = t >> 5, lane = t & 31;
    const uint32_t stg = smem_u32(smem);

    // ---- load A tile into stage (2048 uint4 / 256 thr = 8 iters)
    {
        const uint4* srcA = g_bf16 + I * 2048;
#pragma unroll
        for (int i = 0; i < 8; ++i)
            cp_async16(stg + (i * 256 + t) * 16, srcA + i * 256 + t);
        cp_commit();
    }
    if (t < 128) { redRow[t] = 0.f; }
    else         { redCol[t - 128] = 0.f; }
    if (t < 2) redS[t] = 0.f;
    cp_wait_all();
    __syncthreads();

    // ---- extract A register fragments: warp w rows [16w, 16w+16)
    const int aRow0 = wid * 16 + (lane & 15);
    const int aSub  = lane >> 4;
    uint32_t aF[8][4];                        // [kc][frag]: 32 regs
#pragma unroll
    for (int kc = 0; kc < 8; ++kc) {
        uint32_t addr = stg + aRow0 * 256 + (((2 * kc + aSub) ^ (aRow0 & 7)) << 4);
        ldmatrix_x4(aF[kc][0], aF[kc][1], aF[kc][2], aF[kc][3], addr);
    }
    __syncthreads();      // all warps done reading A before stage reuse for B

    // ---- B pipeline: slice 0 (8KB = 512 uint4 / 256 thr = 2 iters)
    {
        const uint4* srcB = g_bf16 + J * 2048;
#pragma unroll
        for (int i = 0; i < 2; ++i)
            cp_async16(stg + (i * 256 + t) * 16, srcB + i * 256 + t);
        cp_commit();
    }

    const int bRowB = (lane & 7) + ((lane >> 4) << 3);
    const int bSub  = (lane >> 3) & 1;
    const int groupID = lane >> 2, qp = lane & 3;

    float pos = 0.f;
    unsigned long long s2p = 0ull;
    unsigned long long rAcc[2] = {0ull, 0ull};

#pragma unroll 1
    for (int s = 0; s < 4; ++s) {
        cp_wait_all();
        __syncthreads();

        if (s < 3) {
            const uint4* srcB = g_bf16 + J * 2048 + (s + 1) * 512;
            uint32_t dst = stg + (((s + 1) & 1) << 13);
#pragma unroll
            for (int i = 0; i < 2; ++i)
                cp_async16(dst + (i * 256 + t) * 16, srcB + i * 256 + t);
        }
        cp_commit();

        const uint32_t sBa = stg + ((s & 1) << 13);

        float acc[4][4];
#pragma unroll
        for (int ni = 0; ni < 4; ++ni)
#pragma unroll
            for (int k = 0; k < 4; ++k) acc[ni][k] = 0.f;

#pragma unroll
        for (int kc = 0; kc < 8; ++kc) {
            uint32_t b[4][2];
#pragma unroll
            for (int p = 0; p < 2; ++p) {
                int row = bRowB + p * 16;     // 32 local B rows; (row&7) matches global
                uint32_t addr = sBa + row * 256 + (((2 * kc + bSub) ^ (row & 7)) << 4);
                uint32_t r0, r1, r2, r3;
                ldmatrix_x4(r0, r1, r2, r3, addr);
                b[2 * p][0] = r0; b[2 * p][1] = r1;
                b[2 * p + 1][0] = r2; b[2 * p + 1][1] = r3;
            }
#pragma unroll
            for (int ni = 0; ni < 4; ++ni)
                mma_bf16(acc[ni][0], acc[ni][1], acc[ni][2], acc[ni][3],
                         aF[kc][0], aF[kc][1], aF[kc][2], aF[kc][3],
                         b[ni][0], b[ni][1]);
        }

        // ---- epilogue for this 128x32 slice (warp rows 16w..16w+15)
        unsigned long long cAcc[4] = {0ull, 0ull, 0ull, 0ull};
        const bool special = diagT || posT;
        const int r0 = wid * 16 + groupID;
        const int r1 = r0 + 8;
#pragma unroll
        for (int ni = 0; ni < 4; ++ni) {
            float e00 = ex2f(fmaf(acc[ni][0], LOG2E, -LOG2E));
            float e01 = ex2f(fmaf(acc[ni][1], LOG2E, -LOG2E));
            float e10 = ex2f(fmaf(acc[ni][2], LOG2E, -LOG2E));
            float e11 = ex2f(fmaf(acc[ni][3], LOG2E, -LOG2E));
            if (special) {
                e00 = fminf(e00, 1.0f); e01 = fminf(e01, 1.0f);
                e10 = fminf(e10, 1.0f); e11 = fminf(e11, 1.0f);
                const int g0 = s * 32 + ni * 8 + 2 * qp, g1 = g0 + 1;
                if (diagT) {
                    if (r0 == g0) e00 = 1.0f;
                    if (r0 == g1) e01 = 1.0f;
                    if (r1 == g0) e10 = 1.0f;
                    if (r1 == g1) e11 = 1.0f;
                }
                if (posT) {
                    if (r0 == g0) pos += e00;
                    if (r0 == g1) pos += e01;
                    if (r1 == g0) pos += e10;
                    if (r1 == g1) pos += e11;
                }
            }
            unsigned long long p0 = packf2(e00, e01);
            unsigned long long p1 = packf2(e10, e11);
            fma2acc(s2p, p0, p0);
            fma2acc(s2p, p1, p1);
            add2acc(rAcc[0], p0);
            add2acc(rAcc[1], p1);
            add2acc(cAcc[ni], p0);
            add2acc(cAcc[ni], p1);
        }
#pragma unroll
        for (int ni = 0; ni < 4; ++ni) {
            float lo, hi; unpackf2(cAcc[ni], lo, hi);
#pragma unroll
            for (int o = 4; o < 32; o <<= 1) {
                lo += __shfl_xor_sync(0xffffffffu, lo, o);
                hi += __shfl_xor_sync(0xffffffffu, hi, o);
            }
            if (lane < 4) {
                atomicAdd(&redCol[s * 32 + ni * 8 + 2 * qp], lo);
                atomicAdd(&redCol[s * 32 + ni * 8 + 2 * qp + 1], hi);
            }
        }
    }

    // ---- row sums: each row owned by one (wid, h, groupID) -> plain store
#pragma unroll
    for (int h = 0; h < 2; ++h) {
        float lo, hi; unpackf2(rAcc[h], lo, hi);
        float v = lo + hi;
        v += __shfl_xor_sync(0xffffffffu, v, 1);
        v += __shfl_xor_sync(0xffffffffu, v, 2);
        if (qp == 0) redRow[wid * 16 + h * 8 + groupID] = v;
    }
    // scalars
    {
        float lo, hi; unpackf2(s2p, lo, hi);
        float s2 = lo + hi;
#pragma unroll
        for (int o = 16; o; o >>= 1) {
            s2 += __shfl_xor_sync(0xffffffffu, s2, o);
            pos += __shfl_xor_sync(0xffffffffu, pos, o);
        }
        if (lane == 0) {
            atomicAdd(&redS[0], s2);
            if (posT) atomicAdd(&redS[1], pos);
        }
    }
    __syncthreads();

    if (t == 0) {
        double w = diagT ? 1.0 : 2.0;
        atomicAdd(&g_S2, w * (double)redS[0]);
        if (posT) atomicAdd(&g_POS, 2.0 * (double)redS[1]);
    }
    if (t < 128) atomicAdd(&g_rowsum[I * BT + t], (double)redRow[t]);
    else if (!diagT) atomicAdd(&g_rowsum[J * BT + t - 128], (double)redCol[t - 128]);
}

// ---------------- fused rowsum reduction + final combine (ticketed) --------
__global__ void reduce_final_kernel(float* out) {
    const int t = threadIdx.x, wid = t >> 5, lane = t & 31;
    double rv = g_rowsum[blockIdx.x * 128 + t];
    double s1 = rv, s2v = rv * rv;
#pragma unroll
    for (int o = 16; o; o >>= 1) {
        s1  += __shfl_xor_sync(0xffffffffu, s1, o);
        s2v += __shfl_xor_sync(0xffffffffu, s2v, o);
    }
    __shared__ double w1[4], w2[4];
    if (lane == 0) { w1[wid] = s1; w2[wid] = s2v; }
    __syncthreads();
    if (t == 0) {
        atomicAdd(&g_R1, w1[0] + w1[1] + w1[2] + w1[3]);
        atomicAdd(&g_R2, w2[0] + w2[1] + w2[2] + w2[3]);
        __threadfence();
        unsigned tk = atomicAdd(&g_ticket, 1u);
        if (tk == NT - 1) {
            const double Nd = (double)NROWS, Bd = (double)BHALF;
            double S1 = g_R1, S2 = g_S2, POS = g_POS, SR2 = g_R2;
            double trace = Nd;                  // K_ii == 1 exactly
            double neg   = S1 - trace - POS;
            double term1 = POS / (Bd * 2.0);    // B*M*(M-1), M=2
            double term2 = neg / (Bd * Bd * 4.0);
            double scale = Bd / (Bd - 1.0);
            double hsic_zy = scale * (term1 - term2 - 1.0);
            double hsic_zz = (S2 - 2.0 * SR2 / Nd + (S1 / Nd) * (S1 / Nd)) / (Nd * Nd);
            if (hsic_zz < 0.0) hsic_zz = 0.0;
            out[0] = (float)(-hsic_zy + 3.0 * sqrt(hsic_zz));
        }
    }
}

extern "C" void kernel_launch(void* const* d_in, const int* in_sizes, int n_in,
                              void* d_out, int out_size) {
    const float* feat = (const float*)d_in[0];
    float* out = (float*)d_out;

    const int tile_smem = 33800;   // 32K stage/B bufs + redRow + redCol + redS
    cudaFuncSetAttribute(tile_kernel, cudaFuncAttributeMaxDynamicSharedMemorySize, tile_smem);

    prep_kernel<<<(NROWS * 16) / 128, 128>>>(feat);
    tile_kernel<<<NTILES, 256, tile_smem>>>();
    reduce_final_kernel<<<NT, 128>>>(out);
}

// round 13
// speedup vs baseline: 1.5071x; 1.5071x over previous
#include <cuda_runtime.h>
#include <cuda_bf16.h>
#include <math.h>
#include <stdint.h>

#define NROWS 8192
#define DIM   128
#define BHALF 4096
#define BT    128
#define NT    (NROWS / BT)          // 64
#define NTILES (NT * (NT + 1) / 2)  // 2080
#define POS_DELTA (BHALF / BT)      // 32
#define LOG2E 1.4426950408889634f
#define HOIST_KC 6                  // kc 0..5 in regs; kc 6,7 re-LDSM from smem

// ---------------- global scratch (no allocations allowed) ----------------
__device__ double g_S2, g_POS, g_R1, g_R2;
__device__ unsigned g_ticket;
__device__ double g_rowsum[NROWS];
__device__ __align__(16) uint4 g_bf16[NROWS * 16];      // pre-swizzled bf16 rows (256B/row)

// ---------------- prep: init + bf16 convert (norms == 0.5 exactly) ----------
__global__ void prep_kernel(const float* __restrict__ feat) {
    int t = blockIdx.x * blockDim.x + threadIdx.x;   // one uint4 (8 bf16) per thread
    int row = t >> 4;
    int chunk = t & 15;
    const float4* src = reinterpret_cast<const float4*>(feat + row * DIM + chunk * 8);
    float4 a = src[0], b = src[1];
    if (chunk == 0) g_rowsum[row] = 0.0;
    if (t == 0) { g_S2 = 0.0; g_POS = 0.0; g_R1 = 0.0; g_R2 = 0.0; g_ticket = 0u; }

    __nv_bfloat162 p0 = __floats2bfloat162_rn(a.x, a.y);
    __nv_bfloat162 p1 = __floats2bfloat162_rn(a.z, a.w);
    __nv_bfloat162 p2 = __floats2bfloat162_rn(b.x, b.y);
    __nv_bfloat162 p3 = __floats2bfloat162_rn(b.z, b.w);
    uint4 v;
    v.x = *reinterpret_cast<uint32_t*>(&p0);
    v.y = *reinterpret_cast<uint32_t*>(&p1);
    v.z = *reinterpret_cast<uint32_t*>(&p2);
    v.w = *reinterpret_cast<uint32_t*>(&p3);
    g_bf16[row * 16 + (chunk ^ (row & 7))] = v;   // 16B-granular XOR swizzle
}

// ---------------- helpers ----------------
__device__ __forceinline__ uint32_t smem_u32(const void* p) {
    uint32_t a;
    asm("{ .reg .u64 t; cvta.to.shared.u64 t, %1; cvt.u32.u64 %0, t; }" : "=r"(a) : "l"(p));
    return a;
}
__device__ __forceinline__ void cp_async16(uint32_t saddr, const void* gaddr) {
    asm volatile("cp.async.cg.shared.global [%0], [%1], 16;" :: "r"(saddr), "l"(gaddr));
}
__device__ __forceinline__ void cp_commit() {
    asm volatile("cp.async.commit_group;" ::: "memory");
}
__device__ __forceinline__ void cp_wait_all() {
    asm volatile("cp.async.wait_group 0;" ::: "memory");
}
__device__ __forceinline__ void ldmatrix_x4(uint32_t& r0, uint32_t& r1, uint32_t& r2,
                                            uint32_t& r3, uint32_t addr) {
    asm volatile("ldmatrix.sync.aligned.m8n8.x4.shared.b16 {%0,%1,%2,%3}, [%4];"
                 : "=r"(r0), "=r"(r1), "=r"(r2), "=r"(r3) : "r"(addr));
}
__device__ __forceinline__ void mma_bf16(float& c0, float& c1, float& c2, float& c3,
                                         uint32_t a0, uint32_t a1, uint32_t a2, uint32_t a3,
                                         uint32_t b0, uint32_t b1) {
    asm volatile("mma.sync.aligned.m16n8k16.row.col.f32.bf16.bf16.f32 "
                 "{%0,%1,%2,%3}, {%4,%5,%6,%7}, {%8,%9}, {%0,%1,%2,%3};"
                 : "+f"(c0), "+f"(c1), "+f"(c2), "+f"(c3)
                 : "r"(a0), "r"(a1), "r"(a2), "r"(a3), "r"(b0), "r"(b1));
}
__device__ __forceinline__ float ex2f(float x) {
    float r; asm("ex2.approx.f32 %0, %1;" : "=f"(r) : "f"(x)); return r;
}
__device__ __forceinline__ unsigned long long packf2(float lo, float hi) {
    unsigned long long r;
    asm("mov.b64 %0, {%1, %2};" : "=l"(r) : "f"(lo), "f"(hi));
    return r;
}
__device__ __forceinline__ void unpackf2(unsigned long long v, float& lo, float& hi) {
    asm("mov.b64 {%0, %1}, %2;" : "=f"(lo), "=f"(hi) : "l"(v));
}
__device__ __forceinline__ void fma2acc(unsigned long long& acc, unsigned long long a,
                                        unsigned long long b) {
    asm("fma.rn.f32x2 %0, %1, %2, %0;" : "+l"(acc) : "l"(a), "l"(b));
}
__device__ __forceinline__ void add2acc(unsigned long long& acc, unsigned long long a) {
    asm("add.rn.f32x2 %0, %1, %2;" : "=l"(acc) : "l"(a), "l"(acc));
}

// ---------------- fused tile kernel (R8 shape, partial A-hoist, no spills) --
// One CTA (128 thr, 4 warps) = one 128x128 triangular tile. Warp w owns rows
// [32w, 32w+32). A lives in dedicated smem for the whole tile; kc 0..5 A-frags
// are hoisted to registers, kc 6..7 re-LDSM'd per slice. B streamed as four
// 32-col (8KB) slices through a separate 2-buffer cp.async ring.
__global__ __launch_bounds__(128, 4)
void tile_kernel() {
    const int L = blockIdx.x;
    int I = (int)floorf((2.0f * NT + 1.0f
                         - sqrtf((2.0f * NT + 1.0f) * (2.0f * NT + 1.0f) - 8.0f * (float)L))
                        * 0.5f);
    while (I * NT - I * (I - 1) / 2 > L) --I;
    while ((I + 1) * NT - (I + 1) * I / 2 <= L) ++I;
    const int J = I + (L - (I * NT - I * (I - 1) / 2));

    const bool diagT = (I == J);
    const bool posT  = (J == I + POS_DELTA);

    extern __shared__ unsigned char smem[];
    // [0,32K): A (persistent). [32K,48K): B ring (2 x 8KB). [48K,...): reds.
    float* redCol = reinterpret_cast<float*>(smem + 49152);   // [128]
    float* redS   = reinterpret_cast<float*>(smem + 49664);   // [2]: s2, pos

    const int t = threadIdx.x, wid = t >> 5, lane = t & 31;
    const uint32_t sAa  = smem_u32(smem);
    const uint32_t ring = sAa + 32768;

    // ---- load A tile (32KB) + B slice 0 (8KB), one group
    {
        const uint4* srcA = g_bf16 + I * 2048;
#pragma unroll
        for (int i = 0; i < 16; ++i)
            cp_async16(sAa + (i * 128 + t) * 16, srcA + i * 128 + t);
        const uint4* srcB = g_bf16 + J * 2048;
#pragma unroll
        for (int i = 0; i < 4; ++i)
            cp_async16(ring + (i * 128 + t) * 16, srcB + i * 128 + t);
        cp_commit();
    }
    redCol[t] = 0.f;
    if (t < 2) redS[t] = 0.f;
    cp_wait_all();
    __syncthreads();

    // ---- prefetch B slice 1 immediately (overlaps A extraction + slice 0)
    {
        const uint4* srcB = g_bf16 + J * 2048 + 512;
#pragma unroll
        for (int i = 0; i < 4; ++i)
            cp_async16(ring + 8192 + (i * 128 + t) * 16, srcB + i * 128 + t);
        cp_commit();
    }

    // ---- extract A fragments for kc 0..5 (A smem persists: no sync needed)
    const int aRow0 = wid * 32 + (lane & 15);
    const int aSub  = lane >> 4;
    uint32_t aF[HOIST_KC][2][4];              // 48 regs
#pragma unroll
    for (int kc = 0; kc < HOIST_KC; ++kc)
#pragma unroll
        for (int mi = 0; mi < 2; ++mi) {
            int row = aRow0 + mi * 16;
            uint32_t addr = sAa + row * 256 + (((2 * kc + aSub) ^ (row & 7)) << 4);
            ldmatrix_x4(aF[kc][mi][0], aF[kc][mi][1], aF[kc][mi][2], aF[kc][mi][3], addr);
        }

    const int bRowB = (lane & 7) + ((lane >> 4) << 3);
    const int bSub  = (lane >> 3) & 1;
    const int groupID = lane >> 2, qp = lane & 3;

    float pos = 0.f;
    unsigned long long s2p = 0ull;
    unsigned long long rAcc[2][2] = {{0ull, 0ull}, {0ull, 0ull}};

#pragma unroll 1
    for (int s = 0; s < 4; ++s) {
        if (s > 0) {              // slice s buffer was prefetched last iteration
            cp_wait_all();
            __syncthreads();
        }
        if (s > 0 && s < 3) {     // prefetch slice s+1 (slice 1 already in flight)
            const uint4* srcB = g_bf16 + J * 2048 + (s + 1) * 512;
            uint32_t dst = ring + (((s + 1) & 1) << 13);
#pragma unroll
            for (int i = 0; i < 4; ++i)
                cp_async16(dst + (i * 128 + t) * 16, srcB + i * 128 + t);
            cp_commit();
        }

        const uint32_t sBa = ring + ((s & 1) << 13);

        float acc[2][4][4];
#pragma unroll
        for (int mi = 0; mi < 2; ++mi)
#pragma unroll
            for (int ni = 0; ni < 4; ++ni)
#pragma unroll
                for (int k = 0; k < 4; ++k) acc[mi][ni][k] = 0.f;

#pragma unroll
        for (int kc = 0; kc < 8; ++kc) {
            uint32_t a[2][4];
            if (kc < HOIST_KC) {
#pragma unroll
                for (int mi = 0; mi < 2; ++mi)
#pragma unroll
                    for (int k = 0; k < 4; ++k) a[mi][k] = aF[kc][mi][k];
            } else {
#pragma unroll
                for (int mi = 0; mi < 2; ++mi) {
                    int row = aRow0 + mi * 16;
                    uint32_t addr = sAa + row * 256
                                  + (((2 * kc + aSub) ^ (row & 7)) << 4);
                    ldmatrix_x4(a[mi][0], a[mi][1], a[mi][2], a[mi][3], addr);
                }
            }
            uint32_t b[4][2];
#pragma unroll
            for (int p = 0; p < 2; ++p) {
                int row = bRowB + p * 16;     // 32 local B rows; (row&7) matches global
                uint32_t addr = sBa + row * 256 + (((2 * kc + bSub) ^ (row & 7)) << 4);
                uint32_t r0, r1, r2, r3;
                ldmatrix_x4(r0, r1, r2, r3, addr);
                b[2 * p][0] = r0; b[2 * p][1] = r1;
                b[2 * p + 1][0] = r2; b[2 * p + 1][1] = r3;
            }
#pragma unroll
            for (int mi = 0; mi < 2; ++mi)
#pragma unroll
                for (int ni = 0; ni < 4; ++ni)
                    mma_bf16(acc[mi][ni][0], acc[mi][ni][1], acc[mi][ni][2], acc[mi][ni][3],
                             a[mi][0], a[mi][1], a[mi][2], a[mi][3],
                             b[ni][0], b[ni][1]);
        }

        // ---- epilogue for this 128x32 slice
        unsigned long long cAcc[4] = {0ull, 0ull, 0ull, 0ull};
        const bool special = diagT || posT;
#pragma unroll
        for (int mi = 0; mi < 2; ++mi) {
            const int r0 = wid * 32 + mi * 16 + groupID;
            const int r1 = r0 + 8;
#pragma unroll
            for (int ni = 0; ni < 4; ++ni) {
                float e00 = ex2f(fmaf(acc[mi][ni][0], LOG2E, -LOG2E));
                float e01 = ex2f(fmaf(acc[mi][ni][1], LOG2E, -LOG2E));
                float e10 = ex2f(fmaf(acc[mi][ni][2], LOG2E, -LOG2E));
                float e11 = ex2f(fmaf(acc[mi][ni][3], LOG2E, -LOG2E));
                if (special) {
                    e00 = fminf(e00, 1.0f); e01 = fminf(e01, 1.0f);
                    e10 = fminf(e10, 1.0f); e11 = fminf(e11, 1.0f);
                    const int g0 = s * 32 + ni * 8 + 2 * qp, g1 = g0 + 1;
                    if (diagT) {
                        if (r0 == g0) e00 = 1.0f;
                        if (r0 == g1) e01 = 1.0f;
                        if (r1 == g0) e10 = 1.0f;
                        if (r1 == g1) e11 = 1.0f;
                    }
                    if (posT) {
                        if (r0 == g0) pos += e00;
                        if (r0 == g1) pos += e01;
                        if (r1 == g0) pos += e10;
                        if (r1 == g1) pos += e11;
                    }
                }
                unsigned long long p0 = packf2(e00, e01);
                unsigned long long p1 = packf2(e10, e11);
                fma2acc(s2p, p0, p0);
                fma2acc(s2p, p1, p1);
                add2acc(rAcc[mi][0], p0);
                add2acc(rAcc[mi][1], p1);
                add2acc(cAcc[ni], p0);
                add2acc(cAcc[ni], p1);
            }
        }
#pragma unroll
        for (int ni = 0; ni < 4; ++ni) {
            float lo, hi; unpackf2(cAcc[ni], lo, hi);
#pragma unroll
            for (int o = 4; o < 32; o <<= 1) {
                lo += __shfl_xor_sync(0xffffffffu, lo, o);
                hi += __shfl_xor_sync(0xffffffffu, hi, o);
            }
            if (lane < 4) {
                atomicAdd(&redCol[s * 32 + ni * 8 + 2 * qp], lo);
                atomicAdd(&redCol[s * 32 + ni * 8 + 2 * qp + 1], hi);
            }
        }
    }

    // ---- row sums: unique row per (wid, mi, h, groupID) -> direct global atomics
#pragma unroll
    for (int mi = 0; mi < 2; ++mi)
#pragma unroll
        for (int h = 0; h < 2; ++h) {
            float lo, hi; unpackf2(rAcc[mi][h], lo, hi);
            float v = lo + hi;
            v += __shfl_xor_sync(0xffffffffu, v, 1);
            v += __shfl_xor_sync(0xffffffffu, v, 2);
            if (qp == 0)
                atomicAdd(&g_rowsum[I * BT + wid * 32 + mi * 16 + h * 8 + groupID],
                          (double)v);
        }
    // scalars
    {
        float lo, hi; unpackf2(s2p, lo, hi);
        float s2 = lo + hi;
#pragma unroll
        for (int o = 16; o; o >>= 1) {
            s2 += __shfl_xor_sync(0xffffffffu, s2, o);
            pos += __shfl_xor_sync(0xffffffffu, pos, o);
        }
        if (lane == 0) {
            atomicAdd(&redS[0], s2);
            if (posT) atomicAdd(&redS[1], pos);
        }
    }
    __syncthreads();

    if (t == 0) {
        double w = diagT ? 1.0 : 2.0;
        atomicAdd(&g_S2, w * (double)redS[0]);
        if (posT) atomicAdd(&g_POS, 2.0 * (double)redS[1]);
    }
    if (!diagT)
        atomicAdd(&g_rowsum[J * BT + t], (double)redCol[t]);
}

// ---------------- fused rowsum reduction + final combine (ticketed) --------
__global__ void reduce_final_kernel(float* out) {
    const int t = threadIdx.x, wid = t >> 5, lane = t & 31;
    double rv = g_rowsum[blockIdx.x * 128 + t];
    double s1 = rv, s2v = rv * rv;
#pragma unroll
    for (int o = 16; o; o >>= 1) {
        s1  += __shfl_xor_sync(0xffffffffu, s1, o);
        s2v += __shfl_xor_sync(0xffffffffu, s2v, o);
    }
    __shared__ double w1[4], w2[4];
    if (lane == 0) { w1[wid] = s1; w2[wid] = s2v; }
    __syncthreads();
    if (t == 0) {
        atomicAdd(&g_R1, w1[0] + w1[1] + w1[2] + w1[3]);
        atomicAdd(&g_R2, w2[0] + w2[1] + w2[2] + w2[3]);
        __threadfence();
        unsigned tk = atomicAdd(&g_ticket, 1u);
        if (tk == NT - 1) {
            const double Nd = (double)NROWS, Bd = (double)BHALF;
            double S1 = g_R1, S2 = g_S2, POS = g_POS, SR2 = g_R2;
            double trace = Nd;                  // K_ii == 1 exactly
            double neg   = S1 - trace - POS;
            double term1 = POS / (Bd * 2.0);    // B*M*(M-1), M=2
            double term2 = neg / (Bd * Bd * 4.0);
            double scale = Bd / (Bd - 1.0);
            double hsic_zy = scale * (term1 - term2 - 1.0);
            double hsic_zz = (S2 - 2.0 * SR2 / Nd + (S1 / Nd) * (S1 / Nd)) / (Nd * Nd);
            if (hsic_zz < 0.0) hsic_zz = 0.0;
            out[0] = (float)(-hsic_zy + 3.0 * sqrt(hsic_zz));
        }
    }
}

extern "C" void kernel_launch(void* const* d_in, const int* in_sizes, int n_in,
                              void* d_out, int out_size) {
    const float* feat = (const float*)d_in[0];
    float* out = (float*)d_out;

    const int tile_smem = 49672;   // 32K A + 16K B ring + redCol + redS
    cudaFuncSetAttribute(tile_kernel, cudaFuncAttributeMaxDynamicSharedMemorySize, tile_smem);

    prep_kernel<<<(NROWS * 16) / 128, 128>>>(feat);
    tile_kernel<<<NTILES, 128, tile_smem>>>();
    reduce_final_kernel<<<NT, 128>>>(out);
}

// round 14
// speedup vs baseline: 1.5628x; 1.0370x over previous
#include <cuda_runtime.h>
#include <cuda_bf16.h>
#include <math.h>
#include <stdint.h>

#define NROWS 8192
#define DIM   128
#define BHALF 4096
#define BT    128
#define NT    (NROWS / BT)          // 64
#define NTILES (NT * (NT + 1) / 2)  // 2080
#define POS_DELTA (BHALF / BT)      // 32
#define LOG2E 1.4426950408889634f
#define HOIST_KC 6                  // kc 0..5 in regs; kc 6,7 re-LDSM from smem

struct TrueC  { static constexpr bool value = true;  };
struct FalseC { static constexpr bool value = false; };

// ---------------- global scratch (no allocations allowed) ----------------
__device__ double g_S2, g_POS, g_R1, g_R2;
__device__ unsigned g_ticket;
__device__ double g_rowsum[NROWS];
__device__ __align__(16) uint4 g_bf16[NROWS * 16];      // pre-swizzled bf16 rows (256B/row)

// ---------------- prep: init + bf16 convert (norms == 0.5 exactly) ----------
// 262144 threads: one float4 -> one uint2 (8B) each, max warp parallelism.
__global__ void prep_kernel(const float* __restrict__ feat) {
    int t = blockIdx.x * blockDim.x + threadIdx.x;
    int row = t >> 5;
    int sub = t & 31;                 // 4-float group within the row
    int chunk = sub >> 1, half = sub & 1;
    const float4 a = *reinterpret_cast<const float4*>(feat + row * DIM + sub * 4);
    if (sub == 0) g_rowsum[row] = 0.0;
    if (t == 0) { g_S2 = 0.0; g_POS = 0.0; g_R1 = 0.0; g_R2 = 0.0; g_ticket = 0u; }

    __nv_bfloat162 p0 = __floats2bfloat162_rn(a.x, a.y);
    __nv_bfloat162 p1 = __floats2bfloat162_rn(a.z, a.w);
    uint2 v;
    v.x = *reinterpret_cast<uint32_t*>(&p0);
    v.y = *reinterpret_cast<uint32_t*>(&p1);
    int sw = row & 7;
    reinterpret_cast<uint2*>(g_bf16)[row * 32 + (chunk ^ sw) * 2 + half] = v;
}

// ---------------- helpers ----------------
__device__ __forceinline__ uint32_t smem_u32(const void* p) {
    uint32_t a;
    asm("{ .reg .u64 t; cvta.to.shared.u64 t, %1; cvt.u32.u64 %0, t; }" : "=r"(a) : "l"(p));
    return a;
}
__device__ __forceinline__ void cp_async16(uint32_t saddr, const void* gaddr) {
    asm volatile("cp.async.cg.shared.global [%0], [%1], 16;" :: "r"(saddr), "l"(gaddr));
}
__device__ __forceinline__ void cp_commit() {
    asm volatile("cp.async.commit_group;" ::: "memory");
}
__device__ __forceinline__ void cp_wait_all() {
    asm volatile("cp.async.wait_group 0;" ::: "memory");
}
__device__ __forceinline__ void ldmatrix_x4(uint32_t& r0, uint32_t& r1, uint32_t& r2,
                                            uint32_t& r3, uint32_t addr) {
    asm volatile("ldmatrix.sync.aligned.m8n8.x4.shared.b16 {%0,%1,%2,%3}, [%4];"
                 : "=r"(r0), "=r"(r1), "=r"(r2), "=r"(r3) : "r"(addr));
}
__device__ __forceinline__ void mma_bf16(float& c0, float& c1, float& c2, float& c3,
                                         uint32_t a0, uint32_t a1, uint32_t a2, uint32_t a3,
                                         uint32_t b0, uint32_t b1) {
    asm volatile("mma.sync.aligned.m16n8k16.row.col.f32.bf16.bf16.f32 "
                 "{%0,%1,%2,%3}, {%4,%5,%6,%7}, {%8,%9}, {%0,%1,%2,%3};"
                 : "+f"(c0), "+f"(c1), "+f"(c2), "+f"(c3)
                 : "r"(a0), "r"(a1), "r"(a2), "r"(a3), "r"(b0), "r"(b1));
}
__device__ __forceinline__ float ex2f(float x) {
    float r; asm("ex2.approx.f32 %0, %1;" : "=f"(r) : "f"(x)); return r;
}
__device__ __forceinline__ unsigned long long packf2(float lo, float hi) {
    unsigned long long r;
    asm("mov.b64 %0, {%1, %2};" : "=l"(r) : "f"(lo), "f"(hi));
    return r;
}
__device__ __forceinline__ void unpackf2(unsigned long long v, float& lo, float& hi) {
    asm("mov.b64 {%0, %1}, %2;" : "=f"(lo), "=f"(hi) : "l"(v));
}
__device__ __forceinline__ void fma2acc(unsigned long long& acc, unsigned long long a,
                                        unsigned long long b) {
    asm("fma.rn.f32x2 %0, %1, %2, %0;" : "+l"(acc) : "l"(a), "l"(b));
}
__device__ __forceinline__ void add2acc(unsigned long long& acc, unsigned long long a) {
    asm("add.rn.f32x2 %0, %1, %2;" : "=l"(acc) : "l"(a), "l"(acc));
}

// ---------------- fused tile kernel (R13 shape + compile-time special split)
__global__ __launch_bounds__(128, 4)
void tile_kernel() {
    const int L = blockIdx.x;
    int I = (int)floorf((2.0f * NT + 1.0f
                         - sqrtf((2.0f * NT + 1.0f) * (2.0f * NT + 1.0f) - 8.0f * (float)L))
                        * 0.5f);
    while (I * NT - I * (I - 1) / 2 > L) --I;
    while ((I + 1) * NT - (I + 1) * I / 2 <= L) ++I;
    const int J = I + (L - (I * NT - I * (I - 1) / 2));

    const bool diagT = (I == J);
    const bool posT  = (J == I + POS_DELTA);

    extern __shared__ unsigned char smem[];
    // [0,32K): A (persistent). [32K,48K): B ring (2 x 8KB). [48K,...): reds.
    float* redCol = reinterpret_cast<float*>(smem + 49152);   // [128]
    float* redS   = reinterpret_cast<float*>(smem + 49664);   // [2]: s2, pos

    const int t = threadIdx.x, wid = t >> 5, lane = t & 31;
    const uint32_t sAa  = smem_u32(smem);
    const uint32_t ring = sAa + 32768;

    // ---- load A tile (32KB) + B slice 0 (8KB), one group
    {
        const uint4* srcA = g_bf16 + I * 2048;
#pragma unroll
        for (int i = 0; i < 16; ++i)
            cp_async16(sAa + (i * 128 + t) * 16, srcA + i * 128 + t);
        const uint4* srcB = g_bf16 + J * 2048;
#pragma unroll
        for (int i = 0; i < 4; ++i)
            cp_async16(ring + (i * 128 + t) * 16, srcB + i * 128 + t);
        cp_commit();
    }
    redCol[t] = 0.f;
    if (t < 2) redS[t] = 0.f;
    cp_wait_all();
    __syncthreads();

    // ---- prefetch B slice 1 immediately (overlaps A extraction + slice 0)
    {
        const uint4* srcB = g_bf16 + J * 2048 + 512;
#pragma unroll
        for (int i = 0; i < 4; ++i)
            cp_async16(ring + 8192 + (i * 128 + t) * 16, srcB + i * 128 + t);
        cp_commit();
    }

    // ---- extract A fragments for kc 0..5 (A smem persists)
    const int aRow0 = wid * 32 + (lane & 15);
    const int aSub  = lane >> 4;
    uint32_t aF[HOIST_KC][2][4];
#pragma unroll
    for (int kc = 0; kc < HOIST_KC; ++kc)
#pragma unroll
        for (int mi = 0; mi < 2; ++mi) {
            int row = aRow0 + mi * 16;
            uint32_t addr = sAa + row * 256 + (((2 * kc + aSub) ^ (row & 7)) << 4);
            ldmatrix_x4(aF[kc][mi][0], aF[kc][mi][1], aF[kc][mi][2], aF[kc][mi][3], addr);
        }

    const int bRowB = (lane & 7) + ((lane >> 4) << 3);
    const int bSub  = (lane >> 3) & 1;
    const int groupID = lane >> 2, qp = lane & 3;

    float pos = 0.f;
    unsigned long long s2p = 0ull;
    unsigned long long rAcc[2][2] = {{0ull, 0ull}, {0ull, 0ull}};

    auto run_slices = [&](auto SC) {
        constexpr bool SPECIAL = decltype(SC)::value;
#pragma unroll 1
        for (int s = 0; s < 4; ++s) {
            if (s > 0) {          // slice s buffer was prefetched last iteration
                cp_wait_all();
                __syncthreads();
            }
            if (s > 0 && s < 3) { // prefetch slice s+1 (slice 1 already in flight)
                const uint4* srcB = g_bf16 + J * 2048 + (s + 1) * 512;
                uint32_t dst = ring + (((s + 1) & 1) << 13);
#pragma unroll
                for (int i = 0; i < 4; ++i)
                    cp_async16(dst + (i * 128 + t) * 16, srcB + i * 128 + t);
                cp_commit();
            }

            const uint32_t sBa = ring + ((s & 1) << 13);

            float acc[2][4][4];
#pragma unroll
            for (int mi = 0; mi < 2; ++mi)
#pragma unroll
                for (int ni = 0; ni < 4; ++ni)
#pragma unroll
                    for (int k = 0; k < 4; ++k) acc[mi][ni][k] = 0.f;

#pragma unroll
            for (int kc = 0; kc < 8; ++kc) {
                uint32_t a[2][4];
                if (kc < HOIST_KC) {
#pragma unroll
                    for (int mi = 0; mi < 2; ++mi)
#pragma unroll
                        for (int k = 0; k < 4; ++k) a[mi][k] = aF[kc][mi][k];
                } else {
#pragma unroll
                    for (int mi = 0; mi < 2; ++mi) {
                        int row = aRow0 + mi * 16;
                        uint32_t addr = sAa + row * 256
                                      + (((2 * kc + aSub) ^ (row & 7)) << 4);
                        ldmatrix_x4(a[mi][0], a[mi][1], a[mi][2], a[mi][3], addr);
                    }
                }
                uint32_t b[4][2];
#pragma unroll
                for (int p = 0; p < 2; ++p) {
                    int row = bRowB + p * 16;
                    uint32_t addr = sBa + row * 256 + (((2 * kc + bSub) ^ (row & 7)) << 4);
                    uint32_t r0, r1, r2, r3;
                    ldmatrix_x4(r0, r1, r2, r3, addr);
                    b[2 * p][0] = r0; b[2 * p][1] = r1;
                    b[2 * p + 1][0] = r2; b[2 * p + 1][1] = r3;
                }
#pragma unroll
                for (int mi = 0; mi < 2; ++mi)
#pragma unroll
                    for (int ni = 0; ni < 4; ++ni)
                        mma_bf16(acc[mi][ni][0], acc[mi][ni][1], acc[mi][ni][2], acc[mi][ni][3],
                                 a[mi][0], a[mi][1], a[mi][2], a[mi][3],
                                 b[ni][0], b[ni][1]);
            }

            // ---- epilogue for this 128x32 slice
            unsigned long long cAcc[4] = {0ull, 0ull, 0ull, 0ull};
#pragma unroll
            for (int mi = 0; mi < 2; ++mi) {
                const int r0 = wid * 32 + mi * 16 + groupID;
                const int r1 = r0 + 8;
#pragma unroll
                for (int ni = 0; ni < 4; ++ni) {
                    float e00 = ex2f(fmaf(acc[mi][ni][0], LOG2E, -LOG2E));
                    float e01 = ex2f(fmaf(acc[mi][ni][1], LOG2E, -LOG2E));
                    float e10 = ex2f(fmaf(acc[mi][ni][2], LOG2E, -LOG2E));
                    float e11 = ex2f(fmaf(acc[mi][ni][3], LOG2E, -LOG2E));
                    if (SPECIAL) {
                        e00 = fminf(e00, 1.0f); e01 = fminf(e01, 1.0f);
                        e10 = fminf(e10, 1.0f); e11 = fminf(e11, 1.0f);
                        const int g0 = s * 32 + ni * 8 + 2 * qp, g1 = g0 + 1;
                        if (diagT) {
                            if (r0 == g0) e00 = 1.0f;
                            if (r0 == g1) e01 = 1.0f;
                            if (r1 == g0) e10 = 1.0f;
                            if (r1 == g1) e11 = 1.0f;
                        }
                        if (posT) {
                            if (r0 == g0) pos += e00;
                            if (r0 == g1) pos += e01;
                            if (r1 == g0) pos += e10;
                            if (r1 == g1) pos += e11;
                        }
                    }
                    unsigned long long p0 = packf2(e00, e01);
                    unsigned long long p1 = packf2(e10, e11);
                    fma2acc(s2p, p0, p0);
                    fma2acc(s2p, p1, p1);
                    add2acc(rAcc[mi][0], p0);
                    add2acc(rAcc[mi][1], p1);
                    add2acc(cAcc[ni], p0);
                    add2acc(cAcc[ni], p1);
                }
            }
#pragma unroll
            for (int ni = 0; ni < 4; ++ni) {
                float lo, hi; unpackf2(cAcc[ni], lo, hi);
#pragma unroll
                for (int o = 4; o < 32; o <<= 1) {
                    lo += __shfl_xor_sync(0xffffffffu, lo, o);
                    hi += __shfl_xor_sync(0xffffffffu, hi, o);
                }
                if (lane < 4) {
                    atomicAdd(&redCol[s * 32 + ni * 8 + 2 * qp], lo);
                    atomicAdd(&redCol[s * 32 + ni * 8 + 2 * qp + 1], hi);
                }
            }
        }
    };
    if (diagT || posT) run_slices(TrueC{});
    else               run_slices(FalseC{});

    // ---- row sums: unique row per (wid, mi, h, groupID) -> direct global atomics
#pragma unroll
    for (int mi = 0; mi < 2; ++mi)
#pragma unroll
        for (int h = 0; h < 2; ++h) {
            float lo, hi; unpackf2(rAcc[mi][h], lo, hi);
            float v = lo + hi;
            v += __shfl_xor_sync(0xffffffffu, v, 1);
            v += __shfl_xor_sync(0xffffffffu, v, 2);
            if (qp == 0)
                atomicAdd(&g_rowsum[I * BT + wid * 32 + mi * 16 + h * 8 + groupID],
                          (double)v);
        }
    // scalars
    {
        float lo, hi; unpackf2(s2p, lo, hi);
        float s2 = lo + hi;
#pragma unroll
        for (int o = 16; o; o >>= 1) {
            s2 += __shfl_xor_sync(0xffffffffu, s2, o);
            pos += __shfl_xor_sync(0xffffffffu, pos, o);
        }
        if (lane == 0) {
            atomicAdd(&redS[0], s2);
            if (posT) atomicAdd(&redS[1], pos);
        }
    }
    __syncthreads();

    if (t == 0) {
        double w = diagT ? 1.0 : 2.0;
        atomicAdd(&g_S2, w * (double)redS[0]);
        if (posT) atomicAdd(&g_POS, 2.0 * (double)redS[1]);
    }
    if (!diagT)
        atomicAdd(&g_rowsum[J * BT + t], (double)redCol[t]);
}

// ---------------- fused rowsum reduction + final combine (ticketed) --------
__global__ void reduce_final_kernel(float* out) {
    const int t = threadIdx.x, wid = t >> 5, lane = t & 31;
    double rv = g_rowsum[blockIdx.x * 128 + t];
    double s1 = rv, s2v = rv * rv;
#pragma unroll
    for (int o = 16; o; o >>= 1) {
        s1  += __shfl_xor_sync(0xffffffffu, s1, o);
        s2v += __shfl_xor_sync(0xffffffffu, s2v, o);
    }
    __shared__ double w1[4], w2[4];
    if (lane == 0) { w1[wid] = s1; w2[wid] = s2v; }
    __syncthreads();
    if (t == 0) {
        atomicAdd(&g_R1, w1[0] + w1[1] + w1[2] + w1[3]);
        atomicAdd(&g_R2, w2[0] + w2[1] + w2[2] + w2[3]);
        __threadfence();
        unsigned tk = atomicAdd(&g_ticket, 1u);
        if (tk == NT - 1) {
            const double Nd = (double)NROWS, Bd = (double)BHALF;
            double S1 = g_R1, S2 = g_S2, POS = g_POS, SR2 = g_R2;
            double trace = Nd;                  // K_ii == 1 exactly
            double neg   = S1 - trace - POS;
            double term1 = POS / (Bd * 2.0);    // B*M*(M-1), M=2
            double term2 = neg / (Bd * Bd * 4.0);
            double scale = Bd / (Bd - 1.0);
            double hsic_zy = scale * (term1 - term2 - 1.0);
            double hsic_zz = (S2 - 2.0 * SR2 / Nd + (S1 / Nd) * (S1 / Nd)) / (Nd * Nd);
            if (hsic_zz < 0.0) hsic_zz = 0.0;
            out[0] = (float)(-hsic_zy + 3.0 * sqrt(hsic_zz));
        }
    }
}

extern "C" void kernel_launch(void* const* d_in, const int* in_sizes, int n_in,
                              void* d_out, int out_size) {
    const float* feat = (const float*)d_in[0];
    float* out = (float*)d_out;

    const int tile_smem = 49672;   // 32K A + 16K B ring + redCol + redS
    cudaFuncSetAttribute(tile_kernel, cudaFuncAttributeMaxDynamicSharedMemorySize, tile_smem);

    prep_kernel<<<512, 512>>>(feat);
    tile_kernel<<<NTILES, 128, tile_smem>>>();
    reduce_final_kernel<<<NT, 128>>>(out);
}